// round 2
// baseline (speedup 1.0000x reference)
#include <cuda_runtime.h>
#include <cstdint>

// ---------------------------------------------------------------------------
// ModulatedConv2d (StyleGAN2), B=8, Cin=Cout=256, 64x64, k=3, pad=1, demod.
//
// Reformulation: w_b = conv_scale * s_b[i] * d_b[o] * W[o,i,:,:]  (separable)
//   => y_b = (conv_scale * d_b[o]) * conv( s_b[i]*x_b , W )   with SHARED W.
// Pipeline:
//   k_style : s[b,c]  = style[b,:] . (mod_w[c,:]*lin_scale) + mod_b[c]
//   k_w2    : W2[o,i] = conv_scale^2 * sum_tap W[o,i,tap]^2
//   k_scale : scale[b,o] = conv_scale * rsqrt( sum_i s[b,i]^2 * W2[o,i] + 1e-8 )
//   k_conv  : implicit-GEMM conv in TF32 via mma.sync.m16n8k8 (fp32 accum)
// ---------------------------------------------------------------------------

#define BATCH     8
#define IN_CH     256
#define OUT_CH    256
#define STYLE_DIM 512
#define HW        64
#define CONV_SCALE (1.0f / 48.0f)                 /* 1/sqrt(256*9) */
#define LIN_SCALE  (0.044194173824159216f)        /* 1/sqrt(512)   */

// scratch (no cudaMalloc allowed)
__device__ float g_s[BATCH * IN_CH];
__device__ float g_w2[OUT_CH * IN_CH];
__device__ float g_scale[BATCH * OUT_CH];

__device__ __forceinline__ float tf32_round(float x) {
    uint32_t u;
    asm("cvt.rna.tf32.f32 %0, %1;" : "=r"(u) : "f"(x));
    return __uint_as_float(u);
}

// --------------------------- tiny pre-passes -------------------------------

__global__ void k_style(const float* __restrict__ style,
                        const float* __restrict__ mod_w,
                        const float* __restrict__ mod_b) {
    int b = blockIdx.x, c = threadIdx.x;
    __shared__ float4 st[STYLE_DIM / 4];
    if (c < STYLE_DIM / 4)
        st[c] = reinterpret_cast<const float4*>(style + b * STYLE_DIM)[c];
    __syncthreads();
    const float4* wp = reinterpret_cast<const float4*>(mod_w + (size_t)c * STYLE_DIM);
    float acc = 0.f;
#pragma unroll 4
    for (int d = 0; d < STYLE_DIM / 4; d++) {
        float4 a = st[d], w = wp[d];
        acc += a.x * w.x + a.y * w.y + a.z * w.z + a.w * w.w;
    }
    g_s[b * IN_CH + c] = acc * LIN_SCALE + mod_b[c];
}

__global__ void k_w2(const float* __restrict__ weight) {
    int o = blockIdx.x, i = threadIdx.x;
    const float* p = weight + ((size_t)o * IN_CH + i) * 9;
    float s = 0.f;
#pragma unroll
    for (int t = 0; t < 9; t++) s += p[t] * p[t];
    g_w2[o * IN_CH + i] = s * (CONV_SCALE * CONV_SCALE);
}

__global__ void k_scale() {
    int b = blockIdx.x, o = threadIdx.x;
    __shared__ float s2[IN_CH];
    float v = g_s[b * IN_CH + o];
    s2[o] = v * v;
    __syncthreads();
    const float* row = g_w2 + (size_t)o * IN_CH;
    float acc = 0.f;
#pragma unroll 4
    for (int i = 0; i < IN_CH; i++) acc += row[i] * s2[i];
    g_scale[b * OUT_CH + o] = CONV_SCALE * rsqrtf(acc + 1e-8f);
}

// ------------------------------ main conv ----------------------------------
// Block tile: M=128 spatial (8h x 16w), N=128 oc, K looped in 8-ic chunks x 9 taps.
// 256 threads = 8 warps (2 M x 4 N). Warp tile 64x32 = 4x4 m16n8k8 tf32 MMAs.

#define TH   8
#define TW   16
#define NOC  128
#define XH   10
#define XW   18
#define XWP  20      // padded row  -> channel stride 200 (banks conflict-free)
#define SWROW 76     // padded row (72 data): 76*gid + 9*tig mod 32 collision-free

__device__ __forceinline__ void mma_tf32(float (&c)[4],
                                         const uint32_t (&a)[4],
                                         const uint32_t (&b)[2]) {
    asm volatile(
        "mma.sync.aligned.m16n8k8.row.col.f32.tf32.tf32.f32 "
        "{%0,%1,%2,%3},{%4,%5,%6,%7},{%8,%9},{%0,%1,%2,%3};\n"
        : "+f"(c[0]), "+f"(c[1]), "+f"(c[2]), "+f"(c[3])
        : "r"(a[0]), "r"(a[1]), "r"(a[2]), "r"(a[3]), "r"(b[0]), "r"(b[1]));
}

__global__ void __launch_bounds__(256) k_conv(const float* __restrict__ x,
                                              const float* __restrict__ weight,
                                              float* __restrict__ out) {
    __shared__ float sx[8 * XH * XWP];     // 1600 floats
    __shared__ float sw[NOC * SWROW];      // 9728 floats   (total 45.3 KB)

    const int tid  = threadIdx.x;
    const int warp = tid >> 5, lane = tid & 31;
    const int gid  = lane >> 2, tig = lane & 3;
    const int warp_m = warp >> 2;          // 0..1
    const int warp_n = warp & 3;           // 0..3

    const int tile = blockIdx.x;           // 0..31
    const int tw = tile & 3, th = tile >> 2;
    const int h0 = th * TH, w0 = tw * TW;
    const int oc_base = blockIdx.y * NOC;
    const int bb = blockIdx.z;

    const float* xb = x + (size_t)bb * IN_CH * HW * HW;
    const float* sb = g_s + bb * IN_CH;

    float acc[4][4][4];
#pragma unroll
    for (int t = 0; t < 4; t++)
#pragma unroll
        for (int u = 0; u < 4; u++)
#pragma unroll
            for (int r = 0; r < 4; r++) acc[t][u][r] = 0.f;

    for (int ic0 = 0; ic0 < IN_CH; ic0 += 8) {
        __syncthreads();
        // ---- stage x halo tile (s-modulated, tf32-rounded), coalesced ----
        for (int idx = tid; idx < 8 * XH * XW; idx += 256) {
            int c   = idx / (XH * XW);
            int rem = idx - c * (XH * XW);
            int r   = rem / XW, col = rem - r * XW;
            int gh = h0 - 1 + r, gw = w0 - 1 + col;
            float v = 0.f;
            if ((unsigned)gh < (unsigned)HW && (unsigned)gw < (unsigned)HW)
                v = xb[(size_t)(ic0 + c) * (HW * HW) + gh * HW + gw];
            v *= sb[ic0 + c];
            sx[c * (XH * XWP) + r * XWP + col] = tf32_round(v);
        }
        // ---- stage weights [128 oc][8 ic * 9 taps], coalesced rows ----
        for (int idx = tid; idx < NOC * 72; idx += 256) {
            int o = idx / 72, r = idx - o * 72;
            float v = weight[(size_t)(oc_base + o) * (IN_CH * 9) + ic0 * 9 + r];
            sw[o * SWROW + r] = tf32_round(v);
        }
        __syncthreads();

#pragma unroll
        for (int tap = 0; tap < 9; tap++) {
            const int kh = tap / 3, kw = tap - kh * 3;
            uint32_t bfrag[4][2];
#pragma unroll
            for (int u = 0; u < 4; u++) {
                int o_l = warp_n * 32 + u * 8 + gid;
                int q = o_l * SWROW + tig * 9 + tap;
                bfrag[u][0] = __float_as_uint(sw[q]);
                bfrag[u][1] = __float_as_uint(sw[q + 36]);   // ic+4
            }
            uint32_t afrag[4][4];
#pragma unroll
            for (int t = 0; t < 4; t++) {
                int p = tig * (XH * XWP) + (warp_m * 4 + t + kh) * XWP + gid + kw;
                afrag[t][0] = __float_as_uint(sx[p]);                      // row gid
                afrag[t][1] = __float_as_uint(sx[p + 8]);                  // row gid+8 (w+8)
                afrag[t][2] = __float_as_uint(sx[p + 4 * XH * XWP]);       // ic+4
                afrag[t][3] = __float_as_uint(sx[p + 4 * XH * XWP + 8]);
            }
#pragma unroll
            for (int t = 0; t < 4; t++)
#pragma unroll
                for (int u = 0; u < 4; u++)
                    mma_tf32(acc[t][u], afrag[t], bfrag[u]);
        }
    }

    // ---- epilogue: y *= conv_scale * d[b,oc] ----
    float* ob = out + (size_t)bb * OUT_CH * HW * HW;
#pragma unroll
    for (int u = 0; u < 4; u++) {
        int n = oc_base + warp_n * 32 + u * 8 + 2 * tig;
        float sc0 = g_scale[bb * OUT_CH + n];
        float sc1 = g_scale[bb * OUT_CH + n + 1];
#pragma unroll
        for (int t = 0; t < 4; t++) {
            int h = h0 + warp_m * 4 + t;
            int w = w0 + gid;
            float* p = ob + (size_t)n * (HW * HW) + h * HW + w;
            p[0]            = acc[t][u][0] * sc0;   // (n  , h, w)
            p[HW * HW]      = acc[t][u][1] * sc1;   // (n+1, h, w)
            p[8]            = acc[t][u][2] * sc0;   // (n  , h, w+8)
            p[HW * HW + 8]  = acc[t][u][3] * sc1;   // (n+1, h, w+8)
        }
    }
}

// ------------------------------- launch ------------------------------------

extern "C" void kernel_launch(void* const* d_in, const int* in_sizes, int n_in,
                              void* d_out, int out_size) {
    // Map inputs by element count (all five counts are distinct); fall back to
    // metadata positional order (x, style, weight, mod_w, mod_b) if needed.
    const float *x = nullptr, *style = nullptr, *weight = nullptr,
                *mod_w = nullptr, *mod_b = nullptr;
    for (int i = 0; i < n_in; i++) {
        switch (in_sizes[i]) {
            case BATCH * IN_CH * HW * HW:   x      = (const float*)d_in[i]; break;
            case BATCH * STYLE_DIM:         style  = (const float*)d_in[i]; break;
            case OUT_CH * IN_CH * 9:        weight = (const float*)d_in[i]; break;
            case IN_CH * STYLE_DIM:         mod_w  = (const float*)d_in[i]; break;
            case IN_CH:                     mod_b  = (const float*)d_in[i]; break;
            default: break;
        }
    }
    if (!x || !style || !weight || !mod_w || !mod_b) {
        x      = (const float*)d_in[0];
        style  = (const float*)d_in[1];
        weight = (const float*)d_in[2];
        mod_w  = (const float*)d_in[3];
        mod_b  = (const float*)d_in[4];
    }
    float* out = (float*)d_out;

    k_style<<<BATCH, 256>>>(style, mod_w, mod_b);
    k_w2<<<OUT_CH, 256>>>(weight);
    k_scale<<<BATCH, 256>>>();

    dim3 grid(32, OUT_CH / NOC, BATCH);   // 32 spatial tiles x 2 oc tiles x 8 batch
    k_conv<<<grid, 256>>>(x, weight, out);
}

// round 3
// speedup vs baseline: 2.1274x; 2.1274x over previous
#include <cuda_runtime.h>
#include <cstdint>

// ---------------------------------------------------------------------------
// ModulatedConv2d (StyleGAN2), B=8, Cin=Cout=256, 64x64, k=3, pad=1, demod.
// y_b = (conv_scale * d_b[o]) * conv( s_b[i]*x_b , W )  with SHARED W.
// R2: 512-thread CTA (16 warps, 32x32 warp tiles), ping-pong smem pipeline:
//     weights via cp.async.cg, x via register staging (s-modulated, tf32 RNA),
//     1 syncthreads/chunk, cp.async wait after compute.
// ---------------------------------------------------------------------------

#define BATCH     8
#define IN_CH     256
#define OUT_CH    256
#define STYLE_DIM 512
#define HW        64
#define CONV_SCALE (1.0f / 48.0f)                 /* 1/sqrt(256*9) */
#define LIN_SCALE  (0.044194173824159216f)        /* 1/sqrt(512)   */

__device__ float g_s[BATCH * IN_CH];
__device__ float g_w2[OUT_CH * IN_CH];
__device__ float g_scale[BATCH * OUT_CH];

__device__ __forceinline__ float tf32_round(float x) {
    uint32_t u;
    asm("cvt.rna.tf32.f32 %0, %1;" : "=r"(u) : "f"(x));
    return __uint_as_float(u);
}

// --------------------------- tiny pre-passes -------------------------------

__global__ void k_style(const float* __restrict__ style,
                        const float* __restrict__ mod_w,
                        const float* __restrict__ mod_b) {
    int b = blockIdx.x, c = threadIdx.x;
    __shared__ float4 st[STYLE_DIM / 4];
    if (c < STYLE_DIM / 4)
        st[c] = reinterpret_cast<const float4*>(style + b * STYLE_DIM)[c];
    __syncthreads();
    const float4* wp = reinterpret_cast<const float4*>(mod_w + (size_t)c * STYLE_DIM);
    float acc = 0.f;
#pragma unroll 4
    for (int d = 0; d < STYLE_DIM / 4; d++) {
        float4 a = st[d], w = wp[d];
        acc += a.x * w.x + a.y * w.y + a.z * w.z + a.w * w.w;
    }
    g_s[b * IN_CH + c] = acc * LIN_SCALE + mod_b[c];
}

__global__ void k_w2(const float* __restrict__ weight) {
    int o = blockIdx.x, i = threadIdx.x;
    const float* p = weight + ((size_t)o * IN_CH + i) * 9;
    float s = 0.f;
#pragma unroll
    for (int t = 0; t < 9; t++) s += p[t] * p[t];
    g_w2[o * IN_CH + i] = s * (CONV_SCALE * CONV_SCALE);
}

__global__ void k_scale() {
    int b = blockIdx.x, o = threadIdx.x;
    __shared__ float s2[IN_CH];
    float v = g_s[b * IN_CH + o];
    s2[o] = v * v;
    __syncthreads();
    const float* row = g_w2 + (size_t)o * IN_CH;
    float acc = 0.f;
#pragma unroll 4
    for (int i = 0; i < IN_CH; i++) acc += row[i] * s2[i];
    g_scale[b * OUT_CH + o] = CONV_SCALE * rsqrtf(acc + 1e-8f);
}

// ------------------------------ main conv ----------------------------------
// Block tile: M=128 spatial (8h x 16w), N=128 oc, K: 32 chunks of 8 ic x 9 taps.
// 512 threads = 16 warps (4 M x 4 N), warp tile 32x32 = 2x4 m16n8k8 MMAs/k8.

#define TH   8
#define TW   16
#define NOC  128
#define XH   10
#define XW   18
#define XWP  20          // x row pad: channel stride 200 -> conflict-free A loads
#define XBUF (8 * XH * XWP)     // 1600 floats per buffer
#define SWROW 76         // weight row pad (72 data): conflict-free B loads
#define WBUF (NOC * SWROW)      // 9728 floats per buffer
#define SMEM_FLOATS (2 * XBUF + 2 * WBUF)   // 22656 floats = 90624 B

__device__ __forceinline__ void mma_tf32(float (&c)[4],
                                         const uint32_t (&a)[4],
                                         const uint32_t (&b)[2]) {
    asm volatile(
        "mma.sync.aligned.m16n8k8.row.col.f32.tf32.tf32.f32 "
        "{%0,%1,%2,%3},{%4,%5,%6,%7},{%8,%9},{%0,%1,%2,%3};\n"
        : "+f"(c[0]), "+f"(c[1]), "+f"(c[2]), "+f"(c[3])
        : "r"(a[0]), "r"(a[1]), "r"(a[2]), "r"(a[3]), "r"(b[0]), "r"(b[1]));
}

__device__ __forceinline__ void cp_async16(uint32_t s_addr, const float* g_addr) {
    asm volatile("cp.async.cg.shared.global [%0], [%1], 16;\n"
                 :: "r"(s_addr), "l"(g_addr));
}

__global__ void __launch_bounds__(512) k_conv(const float* __restrict__ x,
                                              const float* __restrict__ weight,
                                              float* __restrict__ out) {
    extern __shared__ float smem[];
    float* sx = smem;                 // 2 x 1600
    float* sw = smem + 2 * XBUF;      // 2 x 9728
    const uint32_t sw_b = (uint32_t)__cvta_generic_to_shared(sw);

    const int tid  = threadIdx.x;
    const int warp = tid >> 5, lane = tid & 31;
    const int gid  = lane >> 2, tig = lane & 3;
    const int warp_m = warp >> 2;          // 0..3 (covers 2 h rows each)
    const int warp_n = warp & 3;           // 0..3 (covers 32 oc each)

    const int tile = blockIdx.x;           // 0..31
    const int tw = tile & 3, th = tile >> 2;
    const int h0 = th * TH, w0 = tw * TW;
    const int oc_base = blockIdx.y * NOC;
    const int bb = blockIdx.z;

    const float* xb = x + (size_t)bb * IN_CH * HW * HW;
    const float* wb = weight + (size_t)oc_base * (IN_CH * 9);
    const float* sv = g_s + bb * IN_CH;

    // ---- per-thread x staging metadata (3 elements of the 8x10x18 tile) ----
    int  soff[3], goff[3], cch[3];
    bool act[3];
#pragma unroll
    for (int k = 0; k < 3; k++) {
        int e = tid + k * 512;
        act[k] = (e < 8 * XH * XW);
        int c = 0, r = 0, col = 0;
        if (act[k]) { c = e / (XH * XW); int rem = e - c * (XH * XW);
                      r = rem / XW; col = rem - r * XW; }
        int gh = h0 - 1 + r, gw = w0 - 1 + col;
        bool valid = ((unsigned)gh < (unsigned)HW) & ((unsigned)gw < (unsigned)HW);
        act[k] = act[k] && true;
        soff[k] = c * (XH * XWP) + r * XWP + col;
        goff[k] = valid ? (c * (HW * HW) + gh * HW + gw) : -1;
        cch[k]  = c;
    }

    float xr[3];

    // lambda-ish helpers as macros (keep everything in registers)
#define LOAD_X(IC0)                                                        \
    {                                                                      \
        _Pragma("unroll")                                                  \
        for (int k = 0; k < 3; k++)                                        \
            xr[k] = (act[k] && goff[k] >= 0)                               \
                  ? __ldg(xb + (size_t)(IC0) * (HW * HW) + goff[k]) : 0.f; \
    }
#define STORE_X(IC0, BUF)                                                  \
    {                                                                      \
        float* dst = sx + (BUF) * XBUF;                                    \
        _Pragma("unroll")                                                  \
        for (int k = 0; k < 3; k++)                                        \
            if (act[k])                                                    \
                dst[soff[k]] = tf32_round(xr[k] * __ldg(sv + (IC0) + cch[k])); \
    }
#define CPASYNC_W(IC0, BUF)                                                \
    {                                                                      \
        const float* src0 = wb + (size_t)(IC0) * 9;                        \
        uint32_t dst0 = sw_b + (BUF) * (WBUF * 4);                         \
        for (int g = tid; g < NOC * 18; g += 512) {                        \
            int o = g / 18, j = g - o * 18;                                \
            cp_async16(dst0 + (o * SWROW + j * 4) * 4,                     \
                       src0 + (size_t)o * (IN_CH * 9) + j * 4);            \
        }                                                                  \
        asm volatile("cp.async.commit_group;\n");                          \
    }

    float acc[2][4][4];
#pragma unroll
    for (int t = 0; t < 2; t++)
#pragma unroll
        for (int u = 0; u < 4; u++)
#pragma unroll
            for (int r = 0; r < 4; r++) acc[t][u][r] = 0.f;

    // ---- prologue: stage chunk 0, prefetch x chunk 1 into regs ----
    LOAD_X(0);
    CPASYNC_W(0, 0);
    STORE_X(0, 0);
    LOAD_X(8);
    asm volatile("cp.async.wait_group 0;\n" ::: "memory");
    __syncthreads();

    // precomputed fragment base offsets (buffer-relative)
    const int a_base = tig * (XH * XWP) + warp_m * 2 * XWP + gid;
    const int b_base = (warp_n * 32 + gid) * SWROW + tig * 9;

    for (int i = 0; i < 32; i++) {
        const int cur = i & 1, nxt = cur ^ 1;

        if (i < 31) {
            CPASYNC_W((i + 1) * 8, nxt);
            STORE_X((i + 1) * 8, nxt);
            if (i < 30) LOAD_X((i + 2) * 8);
        }

        // ---- compute chunk i from buffers [cur] ----
        const float* sxc = sx + cur * XBUF;
        const float* swc = sw + cur * WBUF;
#pragma unroll
        for (int tap = 0; tap < 9; tap++) {
            const int kh = tap / 3, kw = tap - kh * 3;
            uint32_t bfrag[4][2];
#pragma unroll
            for (int u = 0; u < 4; u++) {
                int q = b_base + u * 8 * SWROW + tap;
                bfrag[u][0] = __float_as_uint(swc[q]);
                bfrag[u][1] = __float_as_uint(swc[q + 36]);     // ic+4
            }
            uint32_t afrag[2][4];
#pragma unroll
            for (int t = 0; t < 2; t++) {
                int p = a_base + (t + kh) * XWP + kw;
                afrag[t][0] = __float_as_uint(sxc[p]);                    // w=gid
                afrag[t][1] = __float_as_uint(sxc[p + 8]);                // w=gid+8
                afrag[t][2] = __float_as_uint(sxc[p + 4 * XH * XWP]);     // ic+4
                afrag[t][3] = __float_as_uint(sxc[p + 4 * XH * XWP + 8]);
            }
#pragma unroll
            for (int t = 0; t < 2; t++)
#pragma unroll
                for (int u = 0; u < 4; u++)
                    mma_tf32(acc[t][u], afrag[t], bfrag[u]);
        }

        if (i < 31) {
            asm volatile("cp.async.wait_group 0;\n" ::: "memory");
            __syncthreads();
        }
    }

    // ---- epilogue: y *= conv_scale * d[b,oc] ----
    float* ob = out + (size_t)bb * OUT_CH * HW * HW;
#pragma unroll
    for (int u = 0; u < 4; u++) {
        int n = oc_base + warp_n * 32 + u * 8 + 2 * tig;
        float sc0 = g_scale[bb * OUT_CH + n];
        float sc1 = g_scale[bb * OUT_CH + n + 1];
#pragma unroll
        for (int t = 0; t < 2; t++) {
            int h = h0 + warp_m * 2 + t;
            int w = w0 + gid;
            float* p = ob + (size_t)n * (HW * HW) + h * HW + w;
            p[0]            = acc[t][u][0] * sc0;   // (n  , h, w)
            p[HW * HW]      = acc[t][u][1] * sc1;   // (n+1, h, w)
            p[8]            = acc[t][u][2] * sc0;   // (n  , h, w+8)
            p[HW * HW + 8]  = acc[t][u][3] * sc1;   // (n+1, h, w+8)
        }
    }
}

// ------------------------------- launch ------------------------------------

extern "C" void kernel_launch(void* const* d_in, const int* in_sizes, int n_in,
                              void* d_out, int out_size) {
    const float *x = nullptr, *style = nullptr, *weight = nullptr,
                *mod_w = nullptr, *mod_b = nullptr;
    for (int i = 0; i < n_in; i++) {
        switch (in_sizes[i]) {
            case BATCH * IN_CH * HW * HW:   x      = (const float*)d_in[i]; break;
            case BATCH * STYLE_DIM:         style  = (const float*)d_in[i]; break;
            case OUT_CH * IN_CH * 9:        weight = (const float*)d_in[i]; break;
            case IN_CH * STYLE_DIM:         mod_w  = (const float*)d_in[i]; break;
            case IN_CH:                     mod_b  = (const float*)d_in[i]; break;
            default: break;
        }
    }
    if (!x || !style || !weight || !mod_w || !mod_b) {
        x      = (const float*)d_in[0];
        style  = (const float*)d_in[1];
        weight = (const float*)d_in[2];
        mod_w  = (const float*)d_in[3];
        mod_b  = (const float*)d_in[4];
    }
    float* out = (float*)d_out;

    static int smem_set = 0;
    if (!smem_set) {
        cudaFuncSetAttribute(k_conv, cudaFuncAttributeMaxDynamicSharedMemorySize,
                             SMEM_FLOATS * 4);
        smem_set = 1;
    }

    k_style<<<BATCH, 256>>>(style, mod_w, mod_b);
    k_w2<<<OUT_CH, 256>>>(weight);
    k_scale<<<BATCH, 256>>>();

    dim3 grid(32, OUT_CH / NOC, BATCH);   // 32 spatial x 2 oc x 8 batch = 512
    k_conv<<<grid, 512, SMEM_FLOATS * 4>>>(x, weight, out);
}

// round 7
// speedup vs baseline: 2.2504x; 1.0578x over previous
#include <cuda_runtime.h>
#include <cstdint>

// ---------------------------------------------------------------------------
// ModulatedConv2d (StyleGAN2), B=8, Cin=Cout=256, 64x64, k=3, pad=1, demod.
// y_b = (conv_scale * d_b[o]) * conv( s_b[i]*x_b , W )  with SHARED W.
// R6 = R5 resubmitted (prior round: container-level infra failure, no
//     compile/runtime signal; kernel is within the proven R2/R3 envelope).
//     mma.sync TF32 path (tcgen05 unavailable: harness targets plain sm_100).
//     vs R3-best: NOC 128->64 so the CTA fits twice per SM
//     (__launch_bounds__(512,2), smem 50.5KB, regs<=64) -> occ 25%->50%,
//     cross-CTA overlap hides staging/barrier stalls. Ping-pong cp.async
//     weight staging + register-prefetched x staging kept from R3.
// ---------------------------------------------------------------------------

#define BATCH     8
#define IN_CH     256
#define OUT_CH    256
#define STYLE_DIM 512
#define HW        64
#define CONV_SCALE (1.0f / 48.0f)                 /* 1/sqrt(256*9) */
#define LIN_SCALE  (0.044194173824159216f)        /* 1/sqrt(512)   */

__device__ float g_s[BATCH * IN_CH];
__device__ float g_w2[OUT_CH * IN_CH];
__device__ float g_scale[BATCH * OUT_CH];

__device__ __forceinline__ float tf32_round(float x) {
    uint32_t u;
    asm("cvt.rna.tf32.f32 %0, %1;" : "=r"(u) : "f"(x));
    return __uint_as_float(u);
}

// --------------------------- tiny pre-passes -------------------------------

__global__ void k_style(const float* __restrict__ style,
                        const float* __restrict__ mod_w,
                        const float* __restrict__ mod_b) {
    int b = blockIdx.x, t = threadIdx.x;
    int c = t >> 1, half = t & 1;
    __shared__ float4 st[STYLE_DIM / 4];
    if (t < STYLE_DIM / 4)
        st[t] = reinterpret_cast<const float4*>(style + b * STYLE_DIM)[t];
    __syncthreads();
    const float4* wp = reinterpret_cast<const float4*>(mod_w + (size_t)c * STYLE_DIM)
                     + half * 64;
    const float4* sp = st + half * 64;
    float acc = 0.f;
#pragma unroll 4
    for (int d = 0; d < 64; d++) {
        float4 a = sp[d], w = wp[d];
        acc += a.x * w.x + a.y * w.y + a.z * w.z + a.w * w.w;
    }
    acc += __shfl_xor_sync(0xFFFFFFFFu, acc, 1);
    if (!half) g_s[b * IN_CH + c] = acc * LIN_SCALE + mod_b[c];
}

__global__ void k_w2(const float* __restrict__ weight) {
    int o = blockIdx.x, i = threadIdx.x;
    const float* p = weight + ((size_t)o * IN_CH + i) * 9;
    float s = 0.f;
#pragma unroll
    for (int t = 0; t < 9; t++) s += p[t] * p[t];
    g_w2[o * IN_CH + i] = s * (CONV_SCALE * CONV_SCALE);
}

__global__ void k_scale() {
    int b = blockIdx.x, t = threadIdx.x;
    int o = t >> 1, half = t & 1;
    __shared__ float s2[IN_CH];
    if (t < IN_CH) { float v = g_s[b * IN_CH + t]; s2[t] = v * v; }
    __syncthreads();
    const float* row = g_w2 + (size_t)o * IN_CH + half * 128;
    const float* sh  = s2 + half * 128;
    float acc = 0.f;
#pragma unroll 4
    for (int i = 0; i < 128; i++) acc += row[i] * sh[i];
    acc += __shfl_xor_sync(0xFFFFFFFFu, acc, 1);
    if (!half) g_scale[b * OUT_CH + o] = CONV_SCALE * rsqrtf(acc + 1e-8f);
}

// ------------------------------ main conv ----------------------------------
// Block tile: M=128 spatial (8h x 16w), N=64 oc, K: 32 chunks of 8 ic x 9 taps.
// 512 threads = 16 warps (4 M x 4 N), warp tile 32x16 = 2x2 m16n8k8 MMAs/k8.

#define TH   8
#define TW   16
#define NOC  64
#define XH   10
#define XW   18
#define XWP  20          // x row pad: channel stride 200 -> conflict-free A loads
#define XBUF (8 * XH * XWP)     // 1600 floats per buffer
#define SWROW 76         // weight row pad (72 data): conflict-free B loads
#define WBUF (NOC * SWROW)      // 4864 floats per buffer
#define SMEM_FLOATS (2 * XBUF + 2 * WBUF)   // 12928 floats = 51712 B

__device__ __forceinline__ void mma_tf32(float (&c)[4],
                                         const uint32_t (&a)[4],
                                         const uint32_t (&b)[2]) {
    asm volatile(
        "mma.sync.aligned.m16n8k8.row.col.f32.tf32.tf32.f32 "
        "{%0,%1,%2,%3},{%4,%5,%6,%7},{%8,%9},{%0,%1,%2,%3};\n"
        : "+f"(c[0]), "+f"(c[1]), "+f"(c[2]), "+f"(c[3])
        : "r"(a[0]), "r"(a[1]), "r"(a[2]), "r"(a[3]), "r"(b[0]), "r"(b[1]));
}

__device__ __forceinline__ void cp_async16(uint32_t s_addr, const float* g_addr) {
    asm volatile("cp.async.cg.shared.global [%0], [%1], 16;\n"
                 :: "r"(s_addr), "l"(g_addr));
}

__global__ void __launch_bounds__(512, 2) k_conv(const float* __restrict__ x,
                                                 const float* __restrict__ weight,
                                                 float* __restrict__ out) {
    extern __shared__ float smem[];
    float* sx = smem;                 // 2 x 1600
    float* sw = smem + 2 * XBUF;      // 2 x 4864
    const uint32_t sw_b = (uint32_t)__cvta_generic_to_shared(sw);

    const int tid  = threadIdx.x;
    const int warp = tid >> 5, lane = tid & 31;
    const int gid  = lane >> 2, tig = lane & 3;
    const int warp_m = warp >> 2;          // 0..3 (covers 2 h rows each)
    const int warp_n = warp & 3;           // 0..3 (covers 16 oc each)

    const int tile = blockIdx.x;           // 0..31
    const int tw = tile & 3, th = tile >> 2;
    const int h0 = th * TH, w0 = tw * TW;
    const int oc_base = blockIdx.y * NOC;
    const int bb = blockIdx.z;

    const float* xb = x + (size_t)bb * IN_CH * HW * HW;
    const float* wb = weight + (size_t)oc_base * (IN_CH * 9);
    const float* sv = g_s + bb * IN_CH;

    // ---- per-thread x staging metadata (3 elements of the 8x10x18 tile) ----
    int  soff[3], goff[3], cch[3];
    bool act[3];
#pragma unroll
    for (int k = 0; k < 3; k++) {
        int e = tid + k * 512;
        act[k] = (e < 8 * XH * XW);
        int c = 0, r = 0, col = 0;
        if (act[k]) { c = e / (XH * XW); int rem = e - c * (XH * XW);
                      r = rem / XW; col = rem - r * XW; }
        int gh = h0 - 1 + r, gw = w0 - 1 + col;
        bool valid = ((unsigned)gh < (unsigned)HW) & ((unsigned)gw < (unsigned)HW);
        soff[k] = c * (XH * XWP) + r * XWP + col;
        goff[k] = valid ? (c * (HW * HW) + gh * HW + gw) : -1;
        cch[k]  = c;
    }

    float xr[3];

#define LOAD_X(IC0)                                                        \
    {                                                                      \
        _Pragma("unroll")                                                  \
        for (int k = 0; k < 3; k++)                                        \
            xr[k] = (act[k] && goff[k] >= 0)                               \
                  ? __ldg(xb + (size_t)(IC0) * (HW * HW) + goff[k]) : 0.f; \
    }
#define STORE_X(IC0, BUF)                                                  \
    {                                                                      \
        float* dst = sx + (BUF) * XBUF;                                    \
        _Pragma("unroll")                                                  \
        for (int k = 0; k < 3; k++)                                        \
            if (act[k])                                                    \
                dst[soff[k]] = tf32_round(xr[k] * __ldg(sv + (IC0) + cch[k])); \
    }
#define CPASYNC_W(IC0, BUF)                                                \
    {                                                                      \
        const float* src0 = wb + (size_t)(IC0) * 9;                        \
        uint32_t dst0 = sw_b + (BUF) * (WBUF * 4);                         \
        for (int g = tid; g < NOC * 18; g += 512) {                        \
            int o = g / 18, j = g - o * 18;                                \
            cp_async16(dst0 + (o * SWROW + j * 4) * 4,                     \
                       src0 + (size_t)o * (IN_CH * 9) + j * 4);            \
        }                                                                  \
        asm volatile("cp.async.commit_group;\n");                          \
    }

    float acc[2][2][4];
#pragma unroll
    for (int t = 0; t < 2; t++)
#pragma unroll
        for (int u = 0; u < 2; u++)
#pragma unroll
            for (int r = 0; r < 4; r++) acc[t][u][r] = 0.f;

    // ---- prologue: stage chunk 0, prefetch x chunk 1 into regs ----
    LOAD_X(0);
    CPASYNC_W(0, 0);
    STORE_X(0, 0);
    LOAD_X(8);
    asm volatile("cp.async.wait_group 0;\n" ::: "memory");
    __syncthreads();

    // precomputed fragment base offsets (buffer-relative)
    const int a_base = tig * (XH * XWP) + warp_m * 2 * XWP + gid;
    const int b_base = (warp_n * 16 + gid) * SWROW + tig * 9;

    for (int i = 0; i < 32; i++) {
        const int cur = i & 1, nxt = cur ^ 1;

        if (i < 31) {
            CPASYNC_W((i + 1) * 8, nxt);
            STORE_X((i + 1) * 8, nxt);
            if (i < 30) LOAD_X((i + 2) * 8);
        }

        // ---- compute chunk i from buffers [cur] ----
        const float* sxc = sx + cur * XBUF;
        const float* swc = sw + cur * WBUF;
#pragma unroll
        for (int tap = 0; tap < 9; tap++) {
            const int kh = tap / 3, kw = tap - kh * 3;
            uint32_t bfrag[2][2];
#pragma unroll
            for (int u = 0; u < 2; u++) {
                int q = b_base + u * 8 * SWROW + tap;
                bfrag[u][0] = __float_as_uint(swc[q]);
                bfrag[u][1] = __float_as_uint(swc[q + 36]);     // ic+4
            }
            uint32_t afrag[2][4];
#pragma unroll
            for (int t = 0; t < 2; t++) {
                int p = a_base + (t + kh) * XWP + kw;
                afrag[t][0] = __float_as_uint(sxc[p]);                    // w=gid
                afrag[t][1] = __float_as_uint(sxc[p + 8]);                // w=gid+8
                afrag[t][2] = __float_as_uint(sxc[p + 4 * XH * XWP]);     // ic+4
                afrag[t][3] = __float_as_uint(sxc[p + 4 * XH * XWP + 8]);
            }
#pragma unroll
            for (int t = 0; t < 2; t++)
#pragma unroll
                for (int u = 0; u < 2; u++)
                    mma_tf32(acc[t][u], afrag[t], bfrag[u]);
        }

        if (i < 31) {
            asm volatile("cp.async.wait_group 0;\n" ::: "memory");
            __syncthreads();
        }
    }

    // ---- epilogue: y *= conv_scale * d[b,oc] ----
    float* ob = out + (size_t)bb * OUT_CH * HW * HW;
#pragma unroll
    for (int u = 0; u < 2; u++) {
        int n = oc_base + warp_n * 16 + u * 8 + 2 * tig;
        float sc0 = g_scale[bb * OUT_CH + n];
        float sc1 = g_scale[bb * OUT_CH + n + 1];
#pragma unroll
        for (int t = 0; t < 2; t++) {
            int h = h0 + warp_m * 2 + t;
            int w = w0 + gid;
            float* p = ob + (size_t)n * (HW * HW) + h * HW + w;
            p[0]            = acc[t][u][0] * sc0;   // (n  , h, w)
            p[HW * HW]      = acc[t][u][1] * sc1;   // (n+1, h, w)
            p[8]            = acc[t][u][2] * sc0;   // (n  , h, w+8)
            p[HW * HW + 8]  = acc[t][u][3] * sc1;   // (n+1, h, w+8)
        }
    }
}

// ------------------------------- launch ------------------------------------

extern "C" void kernel_launch(void* const* d_in, const int* in_sizes, int n_in,
                              void* d_out, int out_size) {
    const float *x = nullptr, *style = nullptr, *weight = nullptr,
                *mod_w = nullptr, *mod_b = nullptr;
    for (int i = 0; i < n_in; i++) {
        switch (in_sizes[i]) {
            case BATCH * IN_CH * HW * HW:   x      = (const float*)d_in[i]; break;
            case BATCH * STYLE_DIM:         style  = (const float*)d_in[i]; break;
            case OUT_CH * IN_CH * 9:        weight = (const float*)d_in[i]; break;
            case IN_CH * STYLE_DIM:         mod_w  = (const float*)d_in[i]; break;
            case IN_CH:                     mod_b  = (const float*)d_in[i]; break;
            default: break;
        }
    }
    if (!x || !style || !weight || !mod_w || !mod_b) {
        x      = (const float*)d_in[0];
        style  = (const float*)d_in[1];
        weight = (const float*)d_in[2];
        mod_w  = (const float*)d_in[3];
        mod_b  = (const float*)d_in[4];
    }
    float* out = (float*)d_out;

    static int smem_set = 0;
    if (!smem_set) {
        cudaFuncSetAttribute(k_conv, cudaFuncAttributeMaxDynamicSharedMemorySize,
                             SMEM_FLOATS * 4);
        smem_set = 1;
    }

    k_style<<<BATCH, 512>>>(style, mod_w, mod_b);
    k_w2<<<OUT_CH, 256>>>(weight);
    k_scale<<<BATCH, 512>>>();

    dim3 grid(32, OUT_CH / NOC, BATCH);   // 32 spatial x 4 oc x 8 batch = 1024
    k_conv<<<grid, 512, SMEM_FLOATS * 4>>>(x, weight, out);
}

// round 8
// speedup vs baseline: 2.4445x; 1.0863x over previous
#include <cuda_runtime.h>
#include <cstdint>

// ---------------------------------------------------------------------------
// ModulatedConv2d (StyleGAN2), B=8, Cin=Cout=256, 64x64, k=3, pad=1, demod.
// y_b = (conv_scale * d_b[o]) * conv( s_b[i]*x_b , W )  with SHARED W.
// R7: vs R6 (349us, L1-bound at 73.5%): A fragments now loaded with
//     ldmatrix.m8n8.x4 (tf32-as-b16) from a [ichi][18h][18w][ic4] tile
//     -> 72 scalar LDS/warp-chunk become 18 LDSM. B path unchanged
//     (cp.async staging + conflict-free scalar LDS). x staging via
//     4xLDG + STS.128. occ config unchanged (512 thr, 2 CTA/SM).
// ---------------------------------------------------------------------------

#define BATCH     8
#define IN_CH     256
#define OUT_CH    256
#define STYLE_DIM 512
#define HW        64
#define CONV_SCALE (1.0f / 48.0f)                 /* 1/sqrt(256*9) */
#define LIN_SCALE  (0.044194173824159216f)        /* 1/sqrt(512)   */

__device__ float g_s[BATCH * IN_CH];
__device__ float g_w2[OUT_CH * IN_CH];
__device__ float g_scale[BATCH * OUT_CH];

__device__ __forceinline__ float tf32_round(float x) {
    uint32_t u;
    asm("cvt.rna.tf32.f32 %0, %1;" : "=r"(u) : "f"(x));
    return __uint_as_float(u);
}

// --------------------------- tiny pre-passes -------------------------------

__global__ void k_style(const float* __restrict__ style,
                        const float* __restrict__ mod_w,
                        const float* __restrict__ mod_b) {
    int b = blockIdx.x, t = threadIdx.x;
    int c = t >> 1, half = t & 1;
    __shared__ float4 st[STYLE_DIM / 4];
    if (t < STYLE_DIM / 4)
        st[t] = reinterpret_cast<const float4*>(style + b * STYLE_DIM)[t];
    __syncthreads();
    const float4* wp = reinterpret_cast<const float4*>(mod_w + (size_t)c * STYLE_DIM)
                     + half * 64;
    const float4* sp = st + half * 64;
    float acc = 0.f;
#pragma unroll 4
    for (int d = 0; d < 64; d++) {
        float4 a = sp[d], w = wp[d];
        acc += a.x * w.x + a.y * w.y + a.z * w.z + a.w * w.w;
    }
    acc += __shfl_xor_sync(0xFFFFFFFFu, acc, 1);
    if (!half) g_s[b * IN_CH + c] = acc * LIN_SCALE + mod_b[c];
}

__global__ void k_w2(const float* __restrict__ weight) {
    int o = blockIdx.x, i = threadIdx.x;
    const float* p = weight + ((size_t)o * IN_CH + i) * 9;
    float s = 0.f;
#pragma unroll
    for (int t = 0; t < 9; t++) s += p[t] * p[t];
    g_w2[o * IN_CH + i] = s * (CONV_SCALE * CONV_SCALE);
}

__global__ void k_scale() {
    int b = blockIdx.x, t = threadIdx.x;
    int o = t >> 1, half = t & 1;
    __shared__ float s2[IN_CH];
    if (t < IN_CH) { float v = g_s[b * IN_CH + t]; s2[t] = v * v; }
    __syncthreads();
    const float* row = g_w2 + (size_t)o * IN_CH + half * 128;
    const float* sh  = s2 + half * 128;
    float acc = 0.f;
#pragma unroll 4
    for (int i = 0; i < 128; i++) acc += row[i] * sh[i];
    acc += __shfl_xor_sync(0xFFFFFFFFu, acc, 1);
    if (!half) g_scale[b * OUT_CH + o] = CONV_SCALE * rsqrtf(acc + 1e-8f);
}

// ------------------------------ main conv ----------------------------------
// Block tile: M=128 spatial (8h x 16w), N=64 oc, K: 32 chunks of 8 ic x 9 taps.
// 512 threads = 16 warps (4 M x 4 N), warp tile 32x16 = 2x2 m16n8k8 MMAs/k8.
// A via ldmatrix from [ichi][10h][18w][ic4]; B via scalar LDS from [oc][72].

#define TH   8
#define TW   16
#define NOC  64
#define XH   10
#define XW   18
#define XBUF (2 * XH * XW * 4)   // 1440 floats per buffer ([ichi][h][w][ic4])
#define SWROW 76                 // weight row pad (72 data): conflict-free B loads
#define WBUF (NOC * SWROW)       // 4864 floats per buffer
#define SMEM_FLOATS (2 * XBUF + 2 * WBUF)   // 12608 floats = 50432 B

__device__ __forceinline__ void mma_tf32(float (&c)[4],
                                         const uint32_t (&a)[4],
                                         const uint32_t (&b)[2]) {
    asm volatile(
        "mma.sync.aligned.m16n8k8.row.col.f32.tf32.tf32.f32 "
        "{%0,%1,%2,%3},{%4,%5,%6,%7},{%8,%9},{%0,%1,%2,%3};\n"
        : "+f"(c[0]), "+f"(c[1]), "+f"(c[2]), "+f"(c[3])
        : "r"(a[0]), "r"(a[1]), "r"(a[2]), "r"(a[3]), "r"(b[0]), "r"(b[1]));
}

__device__ __forceinline__ void ldsm_x4(uint32_t (&r)[4], uint32_t addr) {
    asm volatile(
        "ldmatrix.sync.aligned.m8n8.x4.shared.b16 {%0,%1,%2,%3}, [%4];"
        : "=r"(r[0]), "=r"(r[1]), "=r"(r[2]), "=r"(r[3]) : "r"(addr));
}

__device__ __forceinline__ void cp_async16(uint32_t s_addr, const float* g_addr) {
    asm volatile("cp.async.cg.shared.global [%0], [%1], 16;\n"
                 :: "r"(s_addr), "l"(g_addr));
}

__global__ void __launch_bounds__(512, 2) k_conv(const float* __restrict__ x,
                                                 const float* __restrict__ weight,
                                                 float* __restrict__ out) {
    extern __shared__ float smem[];
    float* sx = smem;                 // 2 x 1440 ([ichi][10h][18w][4ic])
    float* sw = smem + 2 * XBUF;      // 2 x 4864 ([oc][76])
    const uint32_t sx_b = (uint32_t)__cvta_generic_to_shared(sx);
    const uint32_t sw_b = (uint32_t)__cvta_generic_to_shared(sw);

    const int tid  = threadIdx.x;
    const int warp = tid >> 5, lane = tid & 31;
    const int gid  = lane >> 2, tig = lane & 3;
    const int warp_m = warp >> 2;          // 0..3 (covers 2 h rows each)
    const int warp_n = warp & 3;           // 0..3 (covers 16 oc each)

    const int tile = blockIdx.x;           // 0..31
    const int tw = tile & 3, th = tile >> 2;
    const int h0 = th * TH, w0 = tw * TW;
    const int oc_base = blockIdx.y * NOC;
    const int bb = blockIdx.z;

    const float* xb = x + (size_t)bb * IN_CH * HW * HW;
    const float* wb = weight + (size_t)oc_base * (IN_CH * 9);
    const float* sv = g_s + bb * IN_CH;

    // ---- x staging map: thread handles one (ichi,h,w) site = 4 ic values ----
    // dst (floats) = ichi*720 + (h*18 + w)*4 ; global loads 4 ic @ stride 4096.
    const bool xact = (tid < 2 * XH * XW);            // 360 active
    int x_dst = 0, x_goff = -1, x_icb = 0;
    if (xact) {
        int ichi = tid / (XH * XW), rem = tid - ichi * (XH * XW);
        int h = rem / XW, w = rem - h * XW;
        int gh = h0 - 1 + h, gw = w0 - 1 + w;
        x_dst = ichi * 720 + (h * XW + w) * 4;
        x_icb = ichi * 4;
        x_goff = (((unsigned)gh < (unsigned)HW) && ((unsigned)gw < (unsigned)HW))
               ? (gh * HW + gw) : -1;
    }
    float xr[4];

#define LOAD_X(IC0)                                                        \
    if (xact) {                                                            \
        _Pragma("unroll")                                                  \
        for (int il = 0; il < 4; il++)                                     \
            xr[il] = (x_goff >= 0)                                         \
                ? __ldg(xb + (size_t)((IC0) + x_icb + il) * (HW * HW) + x_goff) \
                : 0.f;                                                     \
    }
#define STORE_X(IC0, BUF)                                                  \
    if (xact) {                                                            \
        float4 v;                                                          \
        v.x = tf32_round(xr[0] * __ldg(sv + (IC0) + x_icb + 0));           \
        v.y = tf32_round(xr[1] * __ldg(sv + (IC0) + x_icb + 1));           \
        v.z = tf32_round(xr[2] * __ldg(sv + (IC0) + x_icb + 2));           \
        v.w = tf32_round(xr[3] * __ldg(sv + (IC0) + x_icb + 3));           \
        *reinterpret_cast<float4*>(sx + (BUF) * XBUF + x_dst) = v;         \
    }
#define CPASYNC_W(IC0, BUF)                                                \
    {                                                                      \
        const float* src0 = wb + (size_t)(IC0) * 9;                        \
        uint32_t dst0 = sw_b + (BUF) * (WBUF * 4);                         \
        for (int g = tid; g < NOC * 18; g += 512) {                        \
            int o = g / 18, j = g - o * 18;                                \
            cp_async16(dst0 + (o * SWROW + j * 4) * 4,                     \
                       src0 + (size_t)o * (IN_CH * 9) + j * 4);            \
        }                                                                  \
        asm volatile("cp.async.commit_group;\n");                          \
    }

    float acc[2][2][4];
#pragma unroll
    for (int t = 0; t < 2; t++)
#pragma unroll
        for (int u = 0; u < 2; u++)
#pragma unroll
            for (int r = 0; r < 4; r++) acc[t][u][r] = 0.f;

    // ---- prologue: stage chunk 0, prefetch x chunk 1 into regs ----
    LOAD_X(0);
    CPASYNC_W(0, 0);
    STORE_X(0, 0);
    LOAD_X(8);
    asm volatile("cp.async.wait_group 0;\n" ::: "memory");
    __syncthreads();

    // ---- ldmatrix per-lane row address (bytes, sx-buffer-relative) ----
    // lane = j*8 + r:  matrix j: (j>>1)=ic-half, (j&1)=m8-half, row r = w.
    // h stride = 288B, w stride = 16B, ichi stride = 2880B.
    const int jj = lane >> 3, rr = lane & 7;
    const uint32_t a_lane = (uint32_t)((jj >> 1) * 2880 + warp_m * 2 * 288
                                       + (rr + (jj & 1) * 8) * 16);
    // B fragment base (floats, sw-buffer-relative)
    const int b_base = (warp_n * 16 + gid) * SWROW + tig * 9;

    for (int i = 0; i < 32; i++) {
        const int cur = i & 1, nxt = cur ^ 1;

        if (i < 31) {
            CPASYNC_W((i + 1) * 8, nxt);
            STORE_X((i + 1) * 8, nxt);
            if (i < 30) LOAD_X((i + 2) * 8);
        }

        // ---- compute chunk i from buffers [cur] ----
        const uint32_t sxa = sx_b + cur * (XBUF * 4) + a_lane;
        const float* swc = sw + cur * WBUF;
#pragma unroll
        for (int tap = 0; tap < 9; tap++) {
            const int kh = tap / 3, kw = tap - kh * 3;
            uint32_t bfrag[2][2];
#pragma unroll
            for (int u = 0; u < 2; u++) {
                int q = b_base + u * 8 * SWROW + tap;
                bfrag[u][0] = __float_as_uint(swc[q]);
                bfrag[u][1] = __float_as_uint(swc[q + 36]);     // ic+4
            }
            uint32_t afrag[2][4];
#pragma unroll
            for (int t = 0; t < 2; t++)
                ldsm_x4(afrag[t], sxa + (uint32_t)((t + kh) * 288 + kw * 16));
#pragma unroll
            for (int t = 0; t < 2; t++)
#pragma unroll
                for (int u = 0; u < 2; u++)
                    mma_tf32(acc[t][u], afrag[t], bfrag[u]);
        }

        if (i < 31) {
            asm volatile("cp.async.wait_group 0;\n" ::: "memory");
            __syncthreads();
        }
    }

    // ---- epilogue: y *= conv_scale * d[b,oc] ----
    float* ob = out + (size_t)bb * OUT_CH * HW * HW;
#pragma unroll
    for (int u = 0; u < 2; u++) {
        int n = oc_base + warp_n * 16 + u * 8 + 2 * tig;
        float sc0 = g_scale[bb * OUT_CH + n];
        float sc1 = g_scale[bb * OUT_CH + n + 1];
#pragma unroll
        for (int t = 0; t < 2; t++) {
            int h = h0 + warp_m * 2 + t;
            int w = w0 + gid;
            float* p = ob + (size_t)n * (HW * HW) + h * HW + w;
            p[0]            = acc[t][u][0] * sc0;   // (n  , h, w)
            p[HW * HW]      = acc[t][u][1] * sc1;   // (n+1, h, w)
            p[8]            = acc[t][u][2] * sc0;   // (n  , h, w+8)
            p[HW * HW + 8]  = acc[t][u][3] * sc1;   // (n+1, h, w+8)
        }
    }
}

// ------------------------------- launch ------------------------------------

extern "C" void kernel_launch(void* const* d_in, const int* in_sizes, int n_in,
                              void* d_out, int out_size) {
    const float *x = nullptr, *style = nullptr, *weight = nullptr,
                *mod_w = nullptr, *mod_b = nullptr;
    for (int i = 0; i < n_in; i++) {
        switch (in_sizes[i]) {
            case BATCH * IN_CH * HW * HW:   x      = (const float*)d_in[i]; break;
            case BATCH * STYLE_DIM:         style  = (const float*)d_in[i]; break;
            case OUT_CH * IN_CH * 9:        weight = (const float*)d_in[i]; break;
            case IN_CH * STYLE_DIM:         mod_w  = (const float*)d_in[i]; break;
            case IN_CH:                     mod_b  = (const float*)d_in[i]; break;
            default: break;
        }
    }
    if (!x || !style || !weight || !mod_w || !mod_b) {
        x      = (const float*)d_in[0];
        style  = (const float*)d_in[1];
        weight = (const float*)d_in[2];
        mod_w  = (const float*)d_in[3];
        mod_b  = (const float*)d_in[4];
    }
    float* out = (float*)d_out;

    static int smem_set = 0;
    if (!smem_set) {
        cudaFuncSetAttribute(k_conv, cudaFuncAttributeMaxDynamicSharedMemorySize,
                             SMEM_FLOATS * 4);
        smem_set = 1;
    }

    k_style<<<BATCH, 512>>>(style, mod_w, mod_b);
    k_w2<<<OUT_CH, 256>>>(weight);
    k_scale<<<BATCH, 512>>>();

    dim3 grid(32, OUT_CH / NOC, BATCH);   // 32 spatial x 4 oc x 8 batch = 1024
    k_conv<<<grid, 512, SMEM_FLOATS * 4>>>(x, weight, out);
}

// round 9
// speedup vs baseline: 2.4899x; 1.0185x over previous
#include <cuda_runtime.h>
#include <cstdint>

// ---------------------------------------------------------------------------
// ModulatedConv2d (StyleGAN2), B=8, Cin=Cout=256, 64x64, k=3, pad=1, demod.
// y_b = (conv_scale * d_b[o]) * conv( s_b[i]*x_b , W )  with SHARED W.
// R8: smem-BANDWIDTH attack (R7 was L1-byte-bound at 79.5%):
//   - warp tile 32x16 -> 64x32 (256 thr, 8 warps, NOC=128): A amortized over
//     N=32, B over M=64  => 384 -> 192 B/MMA.
//   - kw-outer tap loop: A fragments shared across kh (6 LDSM per kw instead
//     of 12)  => A bytes cut another 2x.
//   Total LDS traffic ~0.39x of R7. 2 CTAs/SM via __launch_bounds__(256,2).
//   Proven pieces kept: cp.async B staging, [ichi][h][w][ic4] x tile + ldsm,
//   conflict-free B rows, R3 epilogue mapping.
// ---------------------------------------------------------------------------

#define BATCH     8
#define IN_CH     256
#define OUT_CH    256
#define STYLE_DIM 512
#define HW        64
#define CONV_SCALE (1.0f / 48.0f)                 /* 1/sqrt(256*9) */
#define LIN_SCALE  (0.044194173824159216f)        /* 1/sqrt(512)   */

__device__ float g_s[BATCH * IN_CH];
__device__ float g_w2[OUT_CH * IN_CH];
__device__ float g_scale[BATCH * OUT_CH];

__device__ __forceinline__ float tf32_round(float x) {
    uint32_t u;
    asm("cvt.rna.tf32.f32 %0, %1;" : "=r"(u) : "f"(x));
    return __uint_as_float(u);
}

// --------------------------- tiny pre-passes -------------------------------

__global__ void k_style(const float* __restrict__ style,
                        const float* __restrict__ mod_w,
                        const float* __restrict__ mod_b) {
    int b = blockIdx.x, t = threadIdx.x;
    int c = t >> 1, half = t & 1;
    __shared__ float4 st[STYLE_DIM / 4];
    if (t < STYLE_DIM / 4)
        st[t] = reinterpret_cast<const float4*>(style + b * STYLE_DIM)[t];
    __syncthreads();
    const float4* wp = reinterpret_cast<const float4*>(mod_w + (size_t)c * STYLE_DIM)
                     + half * 64;
    const float4* sp = st + half * 64;
    float acc = 0.f;
#pragma unroll 4
    for (int d = 0; d < 64; d++) {
        float4 a = sp[d], w = wp[d];
        acc += a.x * w.x + a.y * w.y + a.z * w.z + a.w * w.w;
    }
    acc += __shfl_xor_sync(0xFFFFFFFFu, acc, 1);
    if (!half) g_s[b * IN_CH + c] = acc * LIN_SCALE + mod_b[c];
}

__global__ void k_w2(const float* __restrict__ weight) {
    int o = blockIdx.x, i = threadIdx.x;
    const float* p = weight + ((size_t)o * IN_CH + i) * 9;
    float s = 0.f;
#pragma unroll
    for (int t = 0; t < 9; t++) s += p[t] * p[t];
    g_w2[o * IN_CH + i] = s * (CONV_SCALE * CONV_SCALE);
}

__global__ void k_scale() {
    int b = blockIdx.x, t = threadIdx.x;
    int o = t >> 1, half = t & 1;
    __shared__ float s2[IN_CH];
    if (t < IN_CH) { float v = g_s[b * IN_CH + t]; s2[t] = v * v; }
    __syncthreads();
    const float* row = g_w2 + (size_t)o * IN_CH + half * 128;
    const float* sh  = s2 + half * 128;
    float acc = 0.f;
#pragma unroll 4
    for (int i = 0; i < 128; i++) acc += row[i] * sh[i];
    acc += __shfl_xor_sync(0xFFFFFFFFu, acc, 1);
    if (!half) g_scale[b * OUT_CH + o] = CONV_SCALE * rsqrtf(acc + 1e-8f);
}

// ------------------------------ main conv ----------------------------------
// Block tile: M=128 spatial (8h x 16w), N=128 oc, K: 32 chunks of 8 ic x 9 taps.
// 256 threads = 8 warps (2 M x 4 N), warp tile 64x32 = 4x4 m16n8k8 MMAs/tap.
// A via ldmatrix from [ichi][10h][18w][ic4], fragments shared across kh.
// B via conflict-free scalar LDS from [oc][76].

#define TH   8
#define TW   16
#define NOC  128
#define XH   10
#define XW   18
#define XBUF (2 * XH * XW * 4)   // 1440 floats per buffer ([ichi][h][w][ic4])
#define SWROW 76                 // weight row pad (72 data): conflict-free B loads
#define WBUF (NOC * SWROW)       // 9728 floats per buffer
#define SMEM_FLOATS (2 * XBUF + 2 * WBUF)   // 22336 floats = 89344 B

#define NTHREADS 256

__device__ __forceinline__ void mma_tf32(float (&c)[4],
                                         const uint32_t (&a)[4],
                                         const uint32_t (&b)[2]) {
    asm volatile(
        "mma.sync.aligned.m16n8k8.row.col.f32.tf32.tf32.f32 "
        "{%0,%1,%2,%3},{%4,%5,%6,%7},{%8,%9},{%0,%1,%2,%3};\n"
        : "+f"(c[0]), "+f"(c[1]), "+f"(c[2]), "+f"(c[3])
        : "r"(a[0]), "r"(a[1]), "r"(a[2]), "r"(a[3]), "r"(b[0]), "r"(b[1]));
}

__device__ __forceinline__ void ldsm_x4(uint32_t (&r)[4], uint32_t addr) {
    asm volatile(
        "ldmatrix.sync.aligned.m8n8.x4.shared.b16 {%0,%1,%2,%3}, [%4];"
        : "=r"(r[0]), "=r"(r[1]), "=r"(r[2]), "=r"(r[3]) : "r"(addr));
}

__device__ __forceinline__ void cp_async16(uint32_t s_addr, const float* g_addr) {
    asm volatile("cp.async.cg.shared.global [%0], [%1], 16;\n"
                 :: "r"(s_addr), "l"(g_addr));
}

__global__ void __launch_bounds__(NTHREADS, 2) k_conv(const float* __restrict__ x,
                                                      const float* __restrict__ weight,
                                                      float* __restrict__ out) {
    extern __shared__ float smem[];
    float* sx = smem;                 // 2 x 1440 ([ichi][10h][18w][4ic])
    float* sw = smem + 2 * XBUF;      // 2 x 9728 ([oc][76])
    const uint32_t sx_b = (uint32_t)__cvta_generic_to_shared(sx);
    const uint32_t sw_b = (uint32_t)__cvta_generic_to_shared(sw);

    const int tid  = threadIdx.x;
    const int warp = tid >> 5, lane = tid & 31;
    const int gid  = lane >> 2, tig = lane & 3;
    const int warp_m = warp >> 2;          // 0..1 (covers 4 h rows each)
    const int warp_n = warp & 3;           // 0..3 (covers 32 oc each)

    const int tile = blockIdx.x;           // 0..31
    const int tw = tile & 3, th = tile >> 2;
    const int h0 = th * TH, w0 = tw * TW;
    const int oc_base = blockIdx.y * NOC;
    const int bb = blockIdx.z;

    const float* xb = x + (size_t)bb * IN_CH * HW * HW;
    const float* wb = weight + (size_t)oc_base * (IN_CH * 9);
    const float* sv = g_s + bb * IN_CH;

    // ---- x staging map: each site = (ichi,h,w), 4 ic values. 360 sites. ----
    int  x_dst[2], x_goff[2], x_icb[2];
    bool xact[2];
#pragma unroll
    for (int k = 0; k < 2; k++) {
        int e = tid + k * NTHREADS;
        xact[k] = (e < 2 * XH * XW);
        int ichi = 0, h = 0, w = 0;
        if (xact[k]) { ichi = e / (XH * XW); int rem = e - ichi * (XH * XW);
                       h = rem / XW; w = rem - h * XW; }
        int gh = h0 - 1 + h, gw = w0 - 1 + w;
        x_dst[k]  = ichi * 720 + (h * XW + w) * 4;
        x_icb[k]  = ichi * 4;
        x_goff[k] = (((unsigned)gh < (unsigned)HW) && ((unsigned)gw < (unsigned)HW))
                  ? (gh * HW + gw) : -1;
    }
    float xr[2][4];

#define LOAD_X(IC0)                                                        \
    {                                                                      \
        _Pragma("unroll")                                                  \
        for (int k = 0; k < 2; k++)                                        \
            if (xact[k]) {                                                 \
                _Pragma("unroll")                                          \
                for (int il = 0; il < 4; il++)                             \
                    xr[k][il] = (x_goff[k] >= 0)                           \
                        ? __ldg(xb + (size_t)((IC0) + x_icb[k] + il) * (HW * HW) \
                                + x_goff[k])                               \
                        : 0.f;                                             \
            }                                                              \
    }
#define STORE_X(IC0, BUF)                                                  \
    {                                                                      \
        _Pragma("unroll")                                                  \
        for (int k = 0; k < 2; k++)                                        \
            if (xact[k]) {                                                 \
                float4 v;                                                  \
                v.x = tf32_round(xr[k][0] * __ldg(sv + (IC0) + x_icb[k] + 0)); \
                v.y = tf32_round(xr[k][1] * __ldg(sv + (IC0) + x_icb[k] + 1)); \
                v.z = tf32_round(xr[k][2] * __ldg(sv + (IC0) + x_icb[k] + 2)); \
                v.w = tf32_round(xr[k][3] * __ldg(sv + (IC0) + x_icb[k] + 3)); \
                *reinterpret_cast<float4*>(sx + (BUF) * XBUF + x_dst[k]) = v;  \
            }                                                              \
    }
#define CPASYNC_W(IC0, BUF)                                                \
    {                                                                      \
        const float* src0 = wb + (size_t)(IC0) * 9;                        \
        uint32_t dst0 = sw_b + (BUF) * (WBUF * 4);                         \
        for (int g = tid; g < NOC * 18; g += NTHREADS) {                   \
            int o = g / 18, j = g - o * 18;                                \
            cp_async16(dst0 + (o * SWROW + j * 4) * 4,                     \
                       src0 + (size_t)o * (IN_CH * 9) + j * 4);            \
        }                                                                  \
        asm volatile("cp.async.commit_group;\n");                          \
    }

    float acc[4][4][4];
#pragma unroll
    for (int t = 0; t < 4; t++)
#pragma unroll
        for (int u = 0; u < 4; u++)
#pragma unroll
            for (int r = 0; r < 4; r++) acc[t][u][r] = 0.f;

    // ---- prologue: stage chunk 0, prefetch x chunk 1 into regs ----
    LOAD_X(0);
    CPASYNC_W(0, 0);
    STORE_X(0, 0);
    LOAD_X(8);
    asm volatile("cp.async.wait_group 0;\n" ::: "memory");
    __syncthreads();

    // ---- ldmatrix per-lane row address (bytes, sx-buffer-relative) ----
    // lane = j*8 + r:  matrix j: (j>>1)=ic-half, (j&1)=w-half(+8), row r = w.
    // h stride = 288B, w stride = 16B, ichi stride = 2880B.
    const int jj = lane >> 3, rr = lane & 7;
    const uint32_t a_lane = (uint32_t)((jj >> 1) * 2880 + warp_m * 4 * 288
                                       + (rr + (jj & 1) * 8) * 16);
    // B fragment base (floats, sw-buffer-relative); conflict-free (12g+9t mod32)
    const int b_base = (warp_n * 32 + gid) * SWROW + tig * 9;

    for (int i = 0; i < 32; i++) {
        const int cur = i & 1, nxt = cur ^ 1;

        if (i < 31) {
            CPASYNC_W((i + 1) * 8, nxt);
            STORE_X((i + 1) * 8, nxt);
            if (i < 30) LOAD_X((i + 2) * 8);
        }

        // ---- compute chunk i from buffers [cur]: kw outer, A shared over kh ----
        const uint32_t sxa = sx_b + cur * (XBUF * 4) + a_lane;
        const float* swc = sw + cur * WBUF;
#pragma unroll
        for (int kw = 0; kw < 3; kw++) {
            uint32_t afrag[6][4];          // h-rows warp_m*4 + (0..5)
#pragma unroll
            for (int r = 0; r < 6; r++)
                ldsm_x4(afrag[r], sxa + (uint32_t)(r * 288 + kw * 16));
#pragma unroll
            for (int kh = 0; kh < 3; kh++) {
                const int tap = kh * 3 + kw;
                uint32_t bfrag[4][2];
#pragma unroll
                for (int u = 0; u < 4; u++) {
                    int q = b_base + u * 8 * SWROW + tap;
                    bfrag[u][0] = __float_as_uint(swc[q]);
                    bfrag[u][1] = __float_as_uint(swc[q + 36]);   // ic+4
                }
#pragma unroll
                for (int t = 0; t < 4; t++)
#pragma unroll
                    for (int u = 0; u < 4; u++)
                        mma_tf32(acc[t][u], afrag[t + kh], bfrag[u]);
            }
        }

        if (i < 31) {
            asm volatile("cp.async.wait_group 0;\n" ::: "memory");
            __syncthreads();
        }
    }

    // ---- epilogue: y *= conv_scale * d[b,oc] ----
    float* ob = out + (size_t)bb * OUT_CH * HW * HW;
#pragma unroll
    for (int u = 0; u < 4; u++) {
        int n = oc_base + warp_n * 32 + u * 8 + 2 * tig;
        float sc0 = g_scale[bb * OUT_CH + n];
        float sc1 = g_scale[bb * OUT_CH + n + 1];
#pragma unroll
        for (int t = 0; t < 4; t++) {
            int h = h0 + warp_m * 4 + t;
            int w = w0 + gid;
            float* p = ob + (size_t)n * (HW * HW) + h * HW + w;
            p[0]            = acc[t][u][0] * sc0;   // (n  , h, w)
            p[HW * HW]      = acc[t][u][1] * sc1;   // (n+1, h, w)
            p[8]            = acc[t][u][2] * sc0;   // (n  , h, w+8)
            p[HW * HW + 8]  = acc[t][u][3] * sc1;   // (n+1, h, w+8)
        }
    }
}

// ------------------------------- launch ------------------------------------

extern "C" void kernel_launch(void* const* d_in, const int* in_sizes, int n_in,
                              void* d_out, int out_size) {
    const float *x = nullptr, *style = nullptr, *weight = nullptr,
                *mod_w = nullptr, *mod_b = nullptr;
    for (int i = 0; i < n_in; i++) {
        switch (in_sizes[i]) {
            case BATCH * IN_CH * HW * HW:   x      = (const float*)d_in[i]; break;
            case BATCH * STYLE_DIM:         style  = (const float*)d_in[i]; break;
            case OUT_CH * IN_CH * 9:        weight = (const float*)d_in[i]; break;
            case IN_CH * STYLE_DIM:         mod_w  = (const float*)d_in[i]; break;
            case IN_CH:                     mod_b  = (const float*)d_in[i]; break;
            default: break;
        }
    }
    if (!x || !style || !weight || !mod_w || !mod_b) {
        x      = (const float*)d_in[0];
        style  = (const float*)d_in[1];
        weight = (const float*)d_in[2];
        mod_w  = (const float*)d_in[3];
        mod_b  = (const float*)d_in[4];
    }
    float* out = (float*)d_out;

    static int smem_set = 0;
    if (!smem_set) {
        cudaFuncSetAttribute(k_conv, cudaFuncAttributeMaxDynamicSharedMemorySize,
                             SMEM_FLOATS * 4);
        smem_set = 1;
    }

    k_style<<<BATCH, 512>>>(style, mod_w, mod_b);
    k_w2<<<OUT_CH, 256>>>(weight);
    k_scale<<<BATCH, 512>>>();

    dim3 grid(32, OUT_CH / NOC, BATCH);   // 32 spatial x 2 oc x 8 batch = 512
    k_conv<<<grid, NTHREADS, SMEM_FLOATS * 4>>>(x, weight, out);
}